// round 16
// baseline (speedup 1.0000x reference)
#include <cuda_runtime.h>
#include <cstdint>
#include <math.h>

#define SEQ   2048
#define HID   1024
#define THETA 7
#define NBLK_SCAN 32
#define SCAN_THREADS 512
#define ROWS_PER_CTA (HID / NBLK_SCAN)   // 32

// --- scratch (allocation-free: __device__ globals) ---
__device__ float g_pre0[SEQ * HID];                 // pre[0] = x@W_ih^T + internal[0] + b
__device__ unsigned long long g_hp[2][HID];         // packed (tag<<32 | f32 bits), 8B atomic

__device__ __forceinline__ unsigned long long ld_rlx64(const unsigned long long* p) {
    unsigned long long v;
    asm volatile("ld.global.relaxed.gpu.b64 %0, [%1];" : "=l"(v) : "l"(p));
    return v;
}
__device__ __forceinline__ void st_rlx64(unsigned long long* p, unsigned long long v) {
    asm volatile("st.global.relaxed.gpu.b64 [%0], %1;" :: "l"(p), "l"(v) : "memory");
}

// ---------------------------------------------------------------------------
// init: buffer0 = (tag 0, state), buffer1 = (tag INVALID). Replay-safe:
// every slot of both buffers is rewritten on every launch.
// ---------------------------------------------------------------------------
__global__ void init_kernel(const float* __restrict__ state) {
    int i = threadIdx.x;                 // 1024 threads
    g_hp[0][i] = (unsigned long long)__float_as_uint(state[i]);
    g_hp[1][i] = 0xFFFFFFFF00000000ull;
}

// ---------------------------------------------------------------------------
// Fused FFMA GEMM (measured ~94% of f32 FFMA roofline; used for all 8 GEMMs —
// tcgen05 is toolchain-blocked: harness PTX targets sm_103, not sm_103a):
// C[s][j] = f( sum_i A[s][i]*W[j][i] + addp[s][j] + bih[j] + bhh[j] )
// 128x128 tile, BK=16, double-buffered SMEM, register prefetch, 1 sync/iter.
// ---------------------------------------------------------------------------
__global__ __launch_bounds__(256, 1) void gemm_fused(
    const float* __restrict__ A, const float* __restrict__ W,
    const float* __restrict__ addp, const float* __restrict__ bih,
    const float* __restrict__ bhh, float* __restrict__ C,
    int do_tanh, int to_pre0)
{
    __shared__ float As[2][16][128];
    __shared__ float Bs[2][16][128];
    const int tid = threadIdx.x;
    const int M0 = blockIdx.y * 128;
    const int N0 = blockIdx.x * 128;
    const int lr = tid >> 1;            // 0..127 tile row
    const int lc = (tid & 1) << 3;      // 0 or 8 (k offset)
    const int ty = tid >> 4;            // 0..15
    const int tx = tid & 15;            // 0..15

    float acc[8][8];
#pragma unroll
    for (int i = 0; i < 8; i++)
#pragma unroll
        for (int j = 0; j < 8; j++) acc[i][j] = 0.f;

    const float* Ap = A + (size_t)(M0 + lr) * HID + lc;
    const float* Wp = W + (size_t)(N0 + lr) * HID + lc;

    {
        float4 a0 = *(const float4*)(Ap + 0);
        float4 a1 = *(const float4*)(Ap + 4);
        float4 w0 = *(const float4*)(Wp + 0);
        float4 w1 = *(const float4*)(Wp + 4);
        As[0][lc + 0][lr] = a0.x; As[0][lc + 1][lr] = a0.y;
        As[0][lc + 2][lr] = a0.z; As[0][lc + 3][lr] = a0.w;
        As[0][lc + 4][lr] = a1.x; As[0][lc + 5][lr] = a1.y;
        As[0][lc + 6][lr] = a1.z; As[0][lc + 7][lr] = a1.w;
        Bs[0][lc + 0][lr] = w0.x; Bs[0][lc + 1][lr] = w0.y;
        Bs[0][lc + 2][lr] = w0.z; Bs[0][lc + 3][lr] = w0.w;
        Bs[0][lc + 4][lr] = w1.x; Bs[0][lc + 5][lr] = w1.y;
        Bs[0][lc + 6][lr] = w1.z; Bs[0][lc + 7][lr] = w1.w;
    }
    __syncthreads();

    int cur = 0;
    for (int k0 = 0; k0 < HID; k0 += 16) {
        const int has_next = (k0 + 16 < HID);
        float4 a0, a1, w0, w1;
        if (has_next) {
            a0 = *(const float4*)(Ap + k0 + 16);
            a1 = *(const float4*)(Ap + k0 + 20);
            w0 = *(const float4*)(Wp + k0 + 16);
            w1 = *(const float4*)(Wp + k0 + 20);
        }
#pragma unroll
        for (int kk = 0; kk < 16; kk++) {
            float4 af0 = *(const float4*)&As[cur][kk][ty * 8];
            float4 af1 = *(const float4*)&As[cur][kk][ty * 8 + 4];
            float4 bf0 = *(const float4*)&Bs[cur][kk][tx * 8];
            float4 bf1 = *(const float4*)&Bs[cur][kk][tx * 8 + 4];
            float ar[8] = {af0.x, af0.y, af0.z, af0.w, af1.x, af1.y, af1.z, af1.w};
            float br[8] = {bf0.x, bf0.y, bf0.z, bf0.w, bf1.x, bf1.y, bf1.z, bf1.w};
#pragma unroll
            for (int i = 0; i < 8; i++)
#pragma unroll
                for (int j = 0; j < 8; j++) acc[i][j] += ar[i] * br[j];
        }
        if (has_next) {
            const int nxt = cur ^ 1;
            As[nxt][lc + 0][lr] = a0.x; As[nxt][lc + 1][lr] = a0.y;
            As[nxt][lc + 2][lr] = a0.z; As[nxt][lc + 3][lr] = a0.w;
            As[nxt][lc + 4][lr] = a1.x; As[nxt][lc + 5][lr] = a1.y;
            As[nxt][lc + 6][lr] = a1.z; As[nxt][lc + 7][lr] = a1.w;
            Bs[nxt][lc + 0][lr] = w0.x; Bs[nxt][lc + 1][lr] = w0.y;
            Bs[nxt][lc + 2][lr] = w0.z; Bs[nxt][lc + 3][lr] = w0.w;
            Bs[nxt][lc + 4][lr] = w1.x; Bs[nxt][lc + 5][lr] = w1.y;
            Bs[nxt][lc + 6][lr] = w1.z; Bs[nxt][lc + 7][lr] = w1.w;
        }
        __syncthreads();
        cur ^= 1;
    }

    float* Cp = to_pre0 ? g_pre0 : C;
#pragma unroll
    for (int i = 0; i < 8; i++) {
        int row = M0 + ty * 8 + i;
#pragma unroll
        for (int j = 0; j < 8; j++) {
            int col = N0 + tx * 8 + j;
            size_t idx = (size_t)row * HID + col;
            float v = acc[i][j] + addp[idx] + bih[col] + bhh[col];
            if (do_tanh) v = tanhf(v);
            Cp[idx] = v;
        }
    }
}

// ---------------------------------------------------------------------------
// Sequential base-chain scan. 32 CTAs x 512 threads (was 64x256), persistent.
// Rationale: per-step time is gated by the SLOWEST producer (max-over-CTAs);
// halving CTA count halves the skew population and the poll/L2 pressure
// (512 pollers/CTA -> each polls 2 words; broadcast traffic halved).
// Sync protocol unchanged: each h element is one 8-byte atomic word (tag|value),
// st.relaxed.gpu.b64 by the producer, exact-tag polled by consumers. Dot
// partitioning identical to round 14 -> bitwise-identical results.
// ---------------------------------------------------------------------------
__global__ __launch_bounds__(SCAN_THREADS, 1) void scan_kernel(
    const float* __restrict__ W, float* __restrict__ out0,
    float* __restrict__ hT, int write_hT)
{
    const int tid = threadIdx.x;          // 0..511
    const int rlocal = tid >> 4;          // 0..31 row within CTA
    const int lane16 = tid & 15;          // 0..15 chunk within row
    const int j = blockIdx.x * ROWS_PER_CTA + rlocal;

    // strided weight layout: chunk i covers columns i*64 + lane16*4 .. +3
    float4 wreg[16];
#pragma unroll
    for (int i = 0; i < 16; i++)
        wreg[i] = *(const float4*)&W[(size_t)j * HID + i * 64 + lane16 * 4];

    __shared__ float4 hs4[HID / 4];       // full h, staged per step

    float pre = 0.f;
    if (lane16 == 0)
        pre = g_pre0[j];

    for (int s = 0; s < SEQ; s++) {
        // poll this thread's 2 packed words until both carry tag s
        const unsigned long long* base = &g_hp[s & 1][tid * 2];
        const unsigned tag = (unsigned)s;
        unsigned long long w0, w1;
        for (;;) {
            w0 = ld_rlx64(base + 0);
            w1 = ld_rlx64(base + 1);
            if (((unsigned)(w0 >> 32) == tag) & ((unsigned)(w1 >> 32) == tag))
                break;
        }
        ((float2*)hs4)[tid] = make_float2(__uint_as_float((unsigned)w0),
                                          __uint_as_float((unsigned)w1));
        __syncthreads();

        // prefetch pre0 for next step (hides its L2 latency behind compute)
        float pre_next = 0.f;
        if (lane16 == 0 && s + 1 < SEQ)
            pre_next = g_pre0[(size_t)(s + 1) * HID + j];

        // dot: 4 independent accumulators; same order as round 14 (bitwise-equal)
        float a0 = 0.f, a1 = 0.f, a2 = 0.f, a3 = 0.f;
#pragma unroll
        for (int i = 0; i < 16; i += 4) {
            float4 h0 = hs4[(i + 0) * 16 + lane16];
            float4 h1 = hs4[(i + 1) * 16 + lane16];
            float4 h2 = hs4[(i + 2) * 16 + lane16];
            float4 h3 = hs4[(i + 3) * 16 + lane16];
            a0 += wreg[i + 0].x * h0.x + wreg[i + 0].y * h0.y
                + wreg[i + 0].z * h0.z + wreg[i + 0].w * h0.w;
            a1 += wreg[i + 1].x * h1.x + wreg[i + 1].y * h1.y
                + wreg[i + 1].z * h1.z + wreg[i + 1].w * h1.w;
            a2 += wreg[i + 2].x * h2.x + wreg[i + 2].y * h2.y
                + wreg[i + 2].z * h2.z + wreg[i + 2].w * h2.w;
            a3 += wreg[i + 3].x * h3.x + wreg[i + 3].y * h3.y
                + wreg[i + 3].z * h3.z + wreg[i + 3].w * h3.w;
        }
        float acc = (a0 + a1) + (a2 + a3);
        acc += __shfl_xor_sync(0xffffffffu, acc, 8);
        acc += __shfl_xor_sync(0xffffffffu, acc, 4);
        acc += __shfl_xor_sync(0xffffffffu, acc, 2);
        acc += __shfl_xor_sync(0xffffffffu, acc, 1);

        float v = 0.f;
        if (lane16 == 0) {
            v = tanhf(pre + acc);
            // single 8B atomic word: tag (s+1) | value — THE sync event
            st_rlx64(&g_hp[(s + 1) & 1][j],
                     ((unsigned long long)(unsigned)(s + 1) << 32) |
                      (unsigned long long)__float_as_uint(v));
        }
        // output-plane store: off the synchronization chain
        if (lane16 == 0) {
            out0[(size_t)s * HID + j] = v;
            if (write_hT && s == SEQ - 1) hT[j] = v;
        }
        pre = pre_next;
        __syncthreads();                 // protect hs4 before next overwrite
    }
}

// ---------------------------------------------------------------------------
extern "C" void kernel_launch(void* const* d_in, const int* in_sizes, int n_in,
                              void* d_out, int out_size) {
    const float* x        = (const float*)d_in[0];  // [1,2048,1024]
    const float* internal = (const float*)d_in[1];  // [8,2048,1024]
    const float* state    = (const float*)d_in[2];  // [1,1,1024]
    const float* W_ih     = (const float*)d_in[3];  // [1024,1024]
    const float* W_hh     = (const float*)d_in[4];  // [1024,1024]
    const float* b_ih     = (const float*)d_in[5];  // [1024]
    const float* b_hh     = (const float*)d_in[6];  // [1024]
    float* out = (float*)d_out;

    const size_t plane = (size_t)SEQ * HID;
    const int has_tail = (out_size >= (int)((THETA + 1) * plane + HID)) ? 1 : 0;

    init_kernel<<<1, 1024>>>(state);

    dim3 gg(HID / 128, SEQ / 128);
    // pre0 = x @ W_ih^T + internal[0] + b  (no tanh) -> g_pre0
    gemm_fused<<<gg, 256>>>(x, W_ih, internal, b_ih, b_hh, nullptr, 0, 1);

    // sequential base chain -> out plane 0 (+ hT tail)
    scan_kernel<<<NBLK_SCAN, SCAN_THREADS>>>(W_hh, out,
                                             out + (THETA + 1) * plane, has_tail);

    // theta expansion: out[th] = tanh(internal[th] + b + out[th-1] @ W_hh^T)
    for (int th = 1; th <= THETA; th++) {
        gemm_fused<<<gg, 256>>>(out + (size_t)(th - 1) * plane, W_hh,
                                internal + (size_t)th * plane, b_ih, b_hh,
                                out + (size_t)th * plane,
                                /*do_tanh=*/1, /*to_pre0=*/0);
    }
}